// round 8
// baseline (speedup 1.0000x reference)
#include <cuda_runtime.h>

#define CC     120
#define BB     4096
#define PAIRS  (CC * BB)                 // 491520
#define BLOCK  256
#define GRID   592                       // 148 SMs x 4 CTAs -> exactly one wave at occ 4
#define NGROUPS (GRID * BLOCK / 8)       // 18944 eight-lane groups
#define BASE_TRIPS (PAIRS / NGROUPS)     // 25
#define REM    (PAIRS - BASE_TRIPS * NGROUPS)  // 17920 groups take 1 extra trip (% 4 == 0)
#define EPSF   1e-5f

// Streaming x-load with 256B L2 prefetch (dense, fully-consumed stream).
__device__ __forceinline__ float4 ldx(const float4* p) {
    float4 r;
    asm volatile("ld.global.nc.L2::256B.v4.f32 {%0,%1,%2,%3}, [%4];"
                 : "=f"(r.x), "=f"(r.y), "=f"(r.z), "=f"(r.w) : "l"(p));
    return r;
}

// Unhoistable weight load: weights stay in L1 (1.1 KB), zero persistent registers.
__device__ __forceinline__ float4 ldw(const float4* p) {
    float4 r;
    asm volatile("ld.global.nc.v4.f32 {%0,%1,%2,%3}, [%4];"
                 : "=f"(r.x), "=f"(r.y), "=f"(r.z), "=f"(r.w) : "l"(p));
    return r;
}

// Register-free L2 prefetch: pulls DRAM->L2 for the NEXT trip while this trip
// computes, so DRAM demand no longer dips during the compute phase.
__device__ __forceinline__ void pf(const float4* p) {
    asm volatile("prefetch.global.L2 [%0];" :: "l"(p));
}

// d_ki += w[i]*x[k] - w[k]*x[i] for the 6 antisymmetric (k<i) pairs
__device__ __forceinline__ void antisym_acc(const float4 w, const float4 x, float d[6]) {
    d[0] += w.y * x.x - w.x * x.y;
    d[1] += w.z * x.x - w.x * x.z;
    d[2] += w.w * x.x - w.x * x.w;
    d[3] += w.z * x.y - w.y * x.z;
    d[4] += w.w * x.y - w.y * x.w;
    d[5] += w.w * x.z - w.z * x.w;
}

__device__ __forceinline__ float sq6(const float d[6]) {
    return d[0]*d[0] + d[1]*d[1] + d[2]*d[2] + d[3]*d[3] + d[4]*d[4] + d[5]*d[5];
}

__global__ void __launch_bounds__(BLOCK, 4)
ttfc_fused_kernel(const float4* __restrict__ in0,   // [C,B,1,8,4]   f4: p*8 + s
                  const float4* __restrict__ in12,  // [2,C,B,4,8,4] f4: (g*PAIRS+p)*32 + j*8 + s
                  const float4* __restrict__ w0,    // [1,8,4]       f4: s
                  const float4* __restrict__ w12,   // [2,4,8,4]     f4: (g*4+j)*8 + s
                  float* __restrict__ out)          // [B,C]
{
    const int tid = blockIdx.x * BLOCK + threadIdx.x;
    const int s   = tid & 7;
    const int g0  = tid >> 3;
    // Exact split: first REM groups take one extra trip; REM % 4 == 0 keeps the
    // trip count warp-uniform, so full-mask shuffles stay safe.
    const int ntrips = BASE_TRIPS + (g0 < REM ? 1 : 0);

    unsigned u = (unsigned)g0;
#pragma unroll 1
    for (int t = 0; t < ntrips; t++, u += NGROUPS) {
        const int p = (int)u;
        const int b = p & (BB - 1);
        const int c = p >> 12;

        // ---- 9 front-batched streaming LDG.128 per lane (max per-warp MLP):
        //      each is a fully-coalesced 128B line across the 8-lane group ----
        const float4 x0 = ldx(&in0[p * 8 + s]);
        const int baseA = p * 32 + s;              // core12, g = 0
        const int baseB = (PAIRS + p) * 32 + s;    // core12, g = 1
        float4 xA0 = ldx(&in12[baseA + 0]);
        float4 xA1 = ldx(&in12[baseA + 8]);
        float4 xA2 = ldx(&in12[baseA + 16]);
        float4 xA3 = ldx(&in12[baseA + 24]);
        float4 xB0 = ldx(&in12[baseB + 0]);
        float4 xB1 = ldx(&in12[baseB + 8]);
        float4 xB2 = ldx(&in12[baseB + 16]);
        float4 xB3 = ldx(&in12[baseB + 24]);

        // ---- register-free L2 prefetch of NEXT trip (guarded: never past end).
        //      Keeps DRAM busy while this trip waits + computes. ----
        if (t + 1 < ntrips) {
            pf(&in0[p * 8 + s + NGROUPS * 8]);
            pf(&in12[baseA + NGROUPS * 32 + 0]);
            pf(&in12[baseA + NGROUPS * 32 + 8]);
            pf(&in12[baseA + NGROUPS * 32 + 16]);
            pf(&in12[baseA + NGROUPS * 32 + 24]);
            pf(&in12[baseB + NGROUPS * 32 + 0]);
            pf(&in12[baseB + NGROUPS * 32 + 8]);
            pf(&in12[baseB + NGROUPS * 32 + 16]);
            pf(&in12[baseB + NGROUPS * 32 + 24]);
        }

        float acc = 48.0f * (EPSF * EPSF);   // 3 cells x 16*eps^2

        {   // core0
            float d[6] = {0.f, 0.f, 0.f, 0.f, 0.f, 0.f};
            antisym_acc(ldw(&w0[s]), x0, d);
            acc += 0.5f * sq6(d);
        }
        {   // core12, g = 0
            float d[6] = {0.f, 0.f, 0.f, 0.f, 0.f, 0.f};
            const float4* wg = &w12[s];
            antisym_acc(ldw(wg + 0),  xA0, d);
            antisym_acc(ldw(wg + 8),  xA1, d);
            antisym_acc(ldw(wg + 16), xA2, d);
            antisym_acc(ldw(wg + 24), xA3, d);
            acc += 0.5f * sq6(d);
        }
        {   // core12, g = 1
            float d[6] = {0.f, 0.f, 0.f, 0.f, 0.f, 0.f};
            const float4* wg = &w12[32 + s];
            antisym_acc(ldw(wg + 0),  xB0, d);
            antisym_acc(ldw(wg + 8),  xB1, d);
            antisym_acc(ldw(wg + 16), xB2, d);
            antisym_acc(ldw(wg + 24), xB3, d);
            acc += 0.5f * sq6(d);
        }

        // ---- reduce over the 8 s-lanes (warp-uniform trips -> full mask) ----
        acc += __shfl_xor_sync(0xFFFFFFFFu, acc, 1);
        acc += __shfl_xor_sync(0xFFFFFFFFu, acc, 2);
        acc += __shfl_xor_sync(0xFFFFFFFFu, acc, 4);

        if (s == 0) out[b * CC + c] = sqrtf(acc + EPSF);
    }
}

extern "C" void kernel_launch(void* const* d_in, const int* in_sizes, int n_in,
                              void* d_out, int out_size) {
    const float4* in0  = (const float4*)d_in[0];
    const float4* in12 = (const float4*)d_in[1];
    const float4* w0   = (const float4*)d_in[2];
    const float4* w12  = (const float4*)d_in[3];
    float* out = (float*)d_out;

    ttfc_fused_kernel<<<GRID, BLOCK>>>(in0, in12, w0, w12, out);
}

// round 11
// speedup vs baseline: 1.0600x; 1.0600x over previous
#include <cuda_runtime.h>

#define CC     120
#define BB     4096
#define PAIRS  (CC * BB)                 // 491520
#define BLOCK  256
#define GRID   592                       // 148 SMs x 4 CTAs -> exactly one wave
#define NGROUPS (GRID * BLOCK / 8)       // 18944 eight-lane groups
#define TRIPS  ((PAIRS + NGROUPS - 1) / NGROUPS)   // 26 (uniform for all threads)
#define EPSF   1e-5f

// Unhoistable weight load: keeps weights out of the persistent register set.
// 1.1 KB of weights lives in L1 after first touch (~L1-hit latency thereafter).
__device__ __forceinline__ float4 ldw(const float4* p) {
    float4 r;
    asm volatile("ld.global.nc.v4.f32 {%0,%1,%2,%3}, [%4];"
                 : "=f"(r.x), "=f"(r.y), "=f"(r.z), "=f"(r.w) : "l"(p));
    return r;
}

// d_ki += w[i]*x[k] - w[k]*x[i] for the 6 antisymmetric (k<i) pairs
__device__ __forceinline__ void antisym_acc(const float4 w, const float4 x, float d[6]) {
    d[0] += w.y * x.x - w.x * x.y;
    d[1] += w.z * x.x - w.x * x.z;
    d[2] += w.w * x.x - w.x * x.w;
    d[3] += w.z * x.y - w.y * x.z;
    d[4] += w.w * x.y - w.y * x.w;
    d[5] += w.w * x.z - w.z * x.w;
}

__device__ __forceinline__ float sq6(const float d[6]) {
    return d[0]*d[0] + d[1]*d[1] + d[2]*d[2] + d[3]*d[3] + d[4]*d[4] + d[5]*d[5];
}

__global__ void __launch_bounds__(BLOCK, 4)
ttfc_fused_kernel(const float4* __restrict__ in0,   // [C,B,1,8,4]   f4: p*8 + s
                  const float4* __restrict__ in12,  // [2,C,B,4,8,4] f4: (g*PAIRS+p)*32 + j*8 + s
                  const float4* __restrict__ w0,    // [1,8,4]       f4: s
                  const float4* __restrict__ w12,   // [2,4,8,4]     f4: (g*4+j)*8 + s
                  float* __restrict__ out)          // [B,C]
{
    const int tid = blockIdx.x * BLOCK + threadIdx.x;
    const int s   = tid & 7;
    unsigned u = (unsigned)(tid >> 3);

#pragma unroll 1
    for (int t = 0; t < TRIPS; t++, u += NGROUPS) {
        const int p = (u < (unsigned)PAIRS) ? (int)u : (PAIRS - 1);  // clamp: uniform trips
        const int b = p & (BB - 1);
        const int c = p >> 12;

        // ---- front-batched streaming loads: 9 x LDG.128 per lane,
        //      each a fully-coalesced 128B line across the 8-lane group ----
        const float4 x0 = __ldcs(&in0[p * 8 + s]);
        const int baseA = p * 32 + s;              // core12, g = 0
        const int baseB = (PAIRS + p) * 32 + s;    // core12, g = 1
        float4 xA0 = __ldcs(&in12[baseA + 0]);
        float4 xA1 = __ldcs(&in12[baseA + 8]);
        float4 xA2 = __ldcs(&in12[baseA + 16]);
        float4 xA3 = __ldcs(&in12[baseA + 24]);
        float4 xB0 = __ldcs(&in12[baseB + 0]);
        float4 xB1 = __ldcs(&in12[baseB + 8]);
        float4 xB2 = __ldcs(&in12[baseB + 16]);
        float4 xB3 = __ldcs(&in12[baseB + 24]);

        // 3 cells for this lane's s (core0 + two core12 g's): 3 * 16 * eps^2
        float acc = 48.0f * (EPSF * EPSF);

        {   // core0
            float d[6] = {0.f, 0.f, 0.f, 0.f, 0.f, 0.f};
            antisym_acc(ldw(&w0[s]), x0, d);
            acc += 0.5f * sq6(d);
        }
        {   // core12, g = 0
            float d[6] = {0.f, 0.f, 0.f, 0.f, 0.f, 0.f};
            const float4* wg = &w12[s];
            antisym_acc(ldw(wg + 0),  xA0, d);
            antisym_acc(ldw(wg + 8),  xA1, d);
            antisym_acc(ldw(wg + 16), xA2, d);
            antisym_acc(ldw(wg + 24), xA3, d);
            acc += 0.5f * sq6(d);
        }
        {   // core12, g = 1
            float d[6] = {0.f, 0.f, 0.f, 0.f, 0.f, 0.f};
            const float4* wg = &w12[32 + s];
            antisym_acc(ldw(wg + 0),  xB0, d);
            antisym_acc(ldw(wg + 8),  xB1, d);
            antisym_acc(ldw(wg + 16), xB2, d);
            antisym_acc(ldw(wg + 24), xB3, d);
            acc += 0.5f * sq6(d);
        }

        // ---- reduce over the 8 s-lanes (uniform trips -> full mask safe) ----
        acc += __shfl_xor_sync(0xFFFFFFFFu, acc, 1);
        acc += __shfl_xor_sync(0xFFFFFFFFu, acc, 2);
        acc += __shfl_xor_sync(0xFFFFFFFFu, acc, 4);

        // output sectors coalesce in L2 (2MB total fits), write back as full lines
        if (s == 0 && u < (unsigned)PAIRS)
            out[b * CC + c] = sqrtf(acc + EPSF);
    }
}

extern "C" void kernel_launch(void* const* d_in, const int* in_sizes, int n_in,
                              void* d_out, int out_size) {
    const float4* in0  = (const float4*)d_in[0];
    const float4* in12 = (const float4*)d_in[1];
    const float4* w0   = (const float4*)d_in[2];
    const float4* w12  = (const float4*)d_in[3];
    float* out = (float*)d_out;

    ttfc_fused_kernel<<<GRID, BLOCK>>>(in0, in12, w0, w12, out);
}

// round 13
// speedup vs baseline: 1.0843x; 1.0230x over previous
#include <cuda_runtime.h>

#define CC     120
#define BB     4096
#define PAIRS  (CC * BB)                 // 491520
#define BLOCK  256
#define GRID   4736                      // 148 SMs x 32: 8 scheduling waves at occ 4,
                                         // HW work-stealing absorbs per-SM speed spread
#define NGROUPS (GRID * BLOCK / 8)       // 151552 eight-lane groups
#define BASE_TRIPS (PAIRS / NGROUPS)     // 3
#define REM    (PAIRS - BASE_TRIPS * NGROUPS)  // 36864 groups take 1 extra trip (% 4 == 0)
#define EPSF   1e-5f

// Unhoistable weight load: keeps weights out of the persistent register set.
// 1.1 KB of weights lives in L1 after first touch (~L1-hit latency thereafter).
__device__ __forceinline__ float4 ldw(const float4* p) {
    float4 r;
    asm volatile("ld.global.nc.v4.f32 {%0,%1,%2,%3}, [%4];"
                 : "=f"(r.x), "=f"(r.y), "=f"(r.z), "=f"(r.w) : "l"(p));
    return r;
}

// d_ki += w[i]*x[k] - w[k]*x[i] for the 6 antisymmetric (k<i) pairs
__device__ __forceinline__ void antisym_acc(const float4 w, const float4 x, float d[6]) {
    d[0] += w.y * x.x - w.x * x.y;
    d[1] += w.z * x.x - w.x * x.z;
    d[2] += w.w * x.x - w.x * x.w;
    d[3] += w.z * x.y - w.y * x.z;
    d[4] += w.w * x.y - w.y * x.w;
    d[5] += w.w * x.z - w.z * x.w;
}

__device__ __forceinline__ float sq6(const float d[6]) {
    return d[0]*d[0] + d[1]*d[1] + d[2]*d[2] + d[3]*d[3] + d[4]*d[4] + d[5]*d[5];
}

__global__ void __launch_bounds__(BLOCK, 4)
ttfc_fused_kernel(const float4* __restrict__ in0,   // [C,B,1,8,4]   f4: p*8 + s
                  const float4* __restrict__ in12,  // [2,C,B,4,8,4] f4: (g*PAIRS+p)*32 + j*8 + s
                  const float4* __restrict__ w0,    // [1,8,4]       f4: s
                  const float4* __restrict__ w12,   // [2,4,8,4]     f4: (g*4+j)*8 + s
                  float* __restrict__ out)          // [B,C]
{
    const int tid = blockIdx.x * BLOCK + threadIdx.x;
    const int s   = tid & 7;
    const int g0  = tid >> 3;
    // Exact split: first REM groups take one extra trip; REM % 4 == 0 keeps the
    // trip count warp-uniform, so full-mask shuffles stay safe.
    const int ntrips = BASE_TRIPS + (g0 < REM ? 1 : 0);

    unsigned u = (unsigned)g0;
#pragma unroll 1
    for (int t = 0; t < ntrips; t++, u += NGROUPS) {
        const int p = (int)u;
        const int b = p & (BB - 1);
        const int c = p >> 12;

        // ---- front-batched streaming loads: 9 x LDG.128 per lane,
        //      each a fully-coalesced 128B line across the 8-lane group ----
        const float4 x0 = __ldcs(&in0[p * 8 + s]);
        const int baseA = p * 32 + s;              // core12, g = 0
        const int baseB = (PAIRS + p) * 32 + s;    // core12, g = 1
        float4 xA0 = __ldcs(&in12[baseA + 0]);
        float4 xA1 = __ldcs(&in12[baseA + 8]);
        float4 xA2 = __ldcs(&in12[baseA + 16]);
        float4 xA3 = __ldcs(&in12[baseA + 24]);
        float4 xB0 = __ldcs(&in12[baseB + 0]);
        float4 xB1 = __ldcs(&in12[baseB + 8]);
        float4 xB2 = __ldcs(&in12[baseB + 16]);
        float4 xB3 = __ldcs(&in12[baseB + 24]);

        // 3 cells for this lane's s (core0 + two core12 g's): 3 * 16 * eps^2
        float acc = 48.0f * (EPSF * EPSF);

        {   // core0
            float d[6] = {0.f, 0.f, 0.f, 0.f, 0.f, 0.f};
            antisym_acc(ldw(&w0[s]), x0, d);
            acc += 0.5f * sq6(d);
        }
        {   // core12, g = 0
            float d[6] = {0.f, 0.f, 0.f, 0.f, 0.f, 0.f};
            const float4* wg = &w12[s];
            antisym_acc(ldw(wg + 0),  xA0, d);
            antisym_acc(ldw(wg + 8),  xA1, d);
            antisym_acc(ldw(wg + 16), xA2, d);
            antisym_acc(ldw(wg + 24), xA3, d);
            acc += 0.5f * sq6(d);
        }
        {   // core12, g = 1
            float d[6] = {0.f, 0.f, 0.f, 0.f, 0.f, 0.f};
            const float4* wg = &w12[32 + s];
            antisym_acc(ldw(wg + 0),  xB0, d);
            antisym_acc(ldw(wg + 8),  xB1, d);
            antisym_acc(ldw(wg + 16), xB2, d);
            antisym_acc(ldw(wg + 24), xB3, d);
            acc += 0.5f * sq6(d);
        }

        // ---- reduce over the 8 s-lanes (warp-uniform trips -> full mask) ----
        acc += __shfl_xor_sync(0xFFFFFFFFu, acc, 1);
        acc += __shfl_xor_sync(0xFFFFFFFFu, acc, 2);
        acc += __shfl_xor_sync(0xFFFFFFFFu, acc, 4);

        if (s == 0) out[b * CC + c] = sqrtf(acc + EPSF);
    }
}

extern "C" void kernel_launch(void* const* d_in, const int* in_sizes, int n_in,
                              void* d_out, int out_size) {
    const float4* in0  = (const float4*)d_in[0];
    const float4* in12 = (const float4*)d_in[1];
    const float4* w0   = (const float4*)d_in[2];
    const float4* w12  = (const float4*)d_in[3];
    float* out = (float*)d_out;

    ttfc_fused_kernel<<<GRID, BLOCK>>>(in0, in12, w0, w12, out);
}

// round 15
// speedup vs baseline: 1.0976x; 1.0122x over previous
#include <cuda_runtime.h>

#define CC     120
#define BB     4096
#define PAIRS  (CC * BB)                 // 491520
#define BLOCK  256
#define GRID   9472                      // 148 SMs x 64: 16 scheduling waves at occ 4,
                                         // short CTAs -> finer work-stealing, smaller tail
#define NGROUPS (GRID * BLOCK / 8)       // 303104 eight-lane groups
#define BASE_TRIPS (PAIRS / NGROUPS)     // 1
#define REM    (PAIRS - BASE_TRIPS * NGROUPS)  // 188416 groups take 1 extra trip (% 4 == 0)
#define EPSF   1e-5f

// Unhoistable weight load: keeps weights out of the persistent register set.
// 1.1 KB of weights lives in L1 after first touch (L1 persists across CTAs
// within a launch, so later CTAs hit warm L1).
__device__ __forceinline__ float4 ldw(const float4* p) {
    float4 r;
    asm volatile("ld.global.nc.v4.f32 {%0,%1,%2,%3}, [%4];"
                 : "=f"(r.x), "=f"(r.y), "=f"(r.z), "=f"(r.w) : "l"(p));
    return r;
}

// d_ki += w[i]*x[k] - w[k]*x[i] for the 6 antisymmetric (k<i) pairs
__device__ __forceinline__ void antisym_acc(const float4 w, const float4 x, float d[6]) {
    d[0] += w.y * x.x - w.x * x.y;
    d[1] += w.z * x.x - w.x * x.z;
    d[2] += w.w * x.x - w.x * x.w;
    d[3] += w.z * x.y - w.y * x.z;
    d[4] += w.w * x.y - w.y * x.w;
    d[5] += w.w * x.z - w.z * x.w;
}

__device__ __forceinline__ float sq6(const float d[6]) {
    return d[0]*d[0] + d[1]*d[1] + d[2]*d[2] + d[3]*d[3] + d[4]*d[4] + d[5]*d[5];
}

__global__ void __launch_bounds__(BLOCK, 4)
ttfc_fused_kernel(const float4* __restrict__ in0,   // [C,B,1,8,4]   f4: p*8 + s
                  const float4* __restrict__ in12,  // [2,C,B,4,8,4] f4: (g*PAIRS+p)*32 + j*8 + s
                  const float4* __restrict__ w0,    // [1,8,4]       f4: s
                  const float4* __restrict__ w12,   // [2,4,8,4]     f4: (g*4+j)*8 + s
                  float* __restrict__ out)          // [B,C]
{
    const int tid = blockIdx.x * BLOCK + threadIdx.x;
    const int s   = tid & 7;
    const int g0  = tid >> 3;
    // Exact split: first REM groups take one extra trip; REM % 4 == 0 keeps the
    // trip count warp-uniform, so full-mask shuffles stay safe.
    const int ntrips = BASE_TRIPS + (g0 < REM ? 1 : 0);

    unsigned u = (unsigned)g0;
#pragma unroll 1
    for (int t = 0; t < ntrips; t++, u += NGROUPS) {
        const int p = (int)u;
        const int b = p & (BB - 1);
        const int c = p >> 12;

        // ---- front-batched streaming loads: 9 x LDG.128 per lane,
        //      each a fully-coalesced 128B line across the 8-lane group ----
        const float4 x0 = __ldcs(&in0[p * 8 + s]);
        const int baseA = p * 32 + s;              // core12, g = 0
        const int baseB = (PAIRS + p) * 32 + s;    // core12, g = 1
        float4 xA0 = __ldcs(&in12[baseA + 0]);
        float4 xA1 = __ldcs(&in12[baseA + 8]);
        float4 xA2 = __ldcs(&in12[baseA + 16]);
        float4 xA3 = __ldcs(&in12[baseA + 24]);
        float4 xB0 = __ldcs(&in12[baseB + 0]);
        float4 xB1 = __ldcs(&in12[baseB + 8]);
        float4 xB2 = __ldcs(&in12[baseB + 16]);
        float4 xB3 = __ldcs(&in12[baseB + 24]);

        // 3 cells for this lane's s (core0 + two core12 g's): 3 * 16 * eps^2
        float acc = 48.0f * (EPSF * EPSF);

        {   // core0
            float d[6] = {0.f, 0.f, 0.f, 0.f, 0.f, 0.f};
            antisym_acc(ldw(&w0[s]), x0, d);
            acc += 0.5f * sq6(d);
        }
        {   // core12, g = 0
            float d[6] = {0.f, 0.f, 0.f, 0.f, 0.f, 0.f};
            const float4* wg = &w12[s];
            antisym_acc(ldw(wg + 0),  xA0, d);
            antisym_acc(ldw(wg + 8),  xA1, d);
            antisym_acc(ldw(wg + 16), xA2, d);
            antisym_acc(ldw(wg + 24), xA3, d);
            acc += 0.5f * sq6(d);
        }
        {   // core12, g = 1
            float d[6] = {0.f, 0.f, 0.f, 0.f, 0.f, 0.f};
            const float4* wg = &w12[32 + s];
            antisym_acc(ldw(wg + 0),  xB0, d);
            antisym_acc(ldw(wg + 8),  xB1, d);
            antisym_acc(ldw(wg + 16), xB2, d);
            antisym_acc(ldw(wg + 24), xB3, d);
            acc += 0.5f * sq6(d);
        }

        // ---- reduce over the 8 s-lanes (warp-uniform trips -> full mask) ----
        acc += __shfl_xor_sync(0xFFFFFFFFu, acc, 1);
        acc += __shfl_xor_sync(0xFFFFFFFFu, acc, 2);
        acc += __shfl_xor_sync(0xFFFFFFFFu, acc, 4);

        if (s == 0) out[b * CC + c] = sqrtf(acc + EPSF);
    }
}

extern "C" void kernel_launch(void* const* d_in, const int* in_sizes, int n_in,
                              void* d_out, int out_size) {
    const float4* in0  = (const float4*)d_in[0];
    const float4* in12 = (const float4*)d_in[1];
    const float4* w0   = (const float4*)d_in[2];
    const float4* w12  = (const float4*)d_in[3];
    float* out = (float*)d_out;

    ttfc_fused_kernel<<<GRID, BLOCK>>>(in0, in12, w0, w12, out);
}